// round 16
// baseline (speedup 1.0000x reference)
#include <cuda_runtime.h>
#include <cuda_bf16.h>
#include <cuda_fp16.h>

#define DIM 1536
#define NHD 12
#define HD  128
#define SL  6400      // query length (100*8*8)
#define LK  3200      // kv length after even-frame subsample (50*64)
#define TPB 256
#define NKB (LK / 128)   // 25 score col-blocks per row

#define LOSCALE 2048.0f
#define INV_LOSCALE 4.8828125e-4f             // 1/2048
#define INV2_BITS 0x3A0000003A000000ULL       // packed {1/2048, 1/2048}
#define SM_SCALE 0.088388347648318447f        // 1/sqrt(128)
#define LOG2E 1.4426950408889634f
#define SC2 (SM_SCALE * LOG2E)

// ---------------- scratch (static device arrays; no allocs) ----------------
__device__ float g_qraw[SL * DIM];
__device__ float g_kraw[LK * DIM];
__device__ __half g_xh[2][SL * DIM];
__device__ uint2 g_whp[6][(DIM / 4) * DIM];
__device__ uint2 g_wop[2][(DIM / 4) * DIM];
__device__ __nv_bfloat16 g_qb[SL * DIM];
__device__ __nv_bfloat16 g_kb[LK * DIM];
__device__ __nv_bfloat16 g_vb[LK * DIM];
__device__ uint2 g_vpk[(LK / 4) * DIM];
__device__ __nv_bfloat16 g_sc[(size_t)NHD * SL * LK];
__device__ float g_pm[NHD * SL * NKB];
__device__ float g_ps[NHD * SL * NKB];
__device__ float g_M2[NHD * SL];
__device__ float g_iz[NHD * SL];
__device__ __nv_bfloat16 g_aob[SL * DIM];

// ---------------- warp-level MMA helpers ----------------
__device__ __forceinline__ void mma_bf16(float* d, const unsigned* a, const unsigned* b)
{
    asm volatile(
        "mma.sync.aligned.m16n8k16.row.col.f32.bf16.bf16.f32 "
        "{%0,%1,%2,%3}, {%4,%5,%6,%7}, {%8,%9}, {%0,%1,%2,%3};\n"
        : "+f"(d[0]), "+f"(d[1]), "+f"(d[2]), "+f"(d[3])
        : "r"(a[0]), "r"(a[1]), "r"(a[2]), "r"(a[3]), "r"(b[0]), "r"(b[1]));
}

__device__ __forceinline__ void mma_f16(float* d, const unsigned* a, const unsigned* b)
{
    asm volatile(
        "mma.sync.aligned.m16n8k16.row.col.f32.f16.f16.f32 "
        "{%0,%1,%2,%3}, {%4,%5,%6,%7}, {%8,%9}, {%0,%1,%2,%3};\n"
        : "+f"(d[0]), "+f"(d[1]), "+f"(d[2]), "+f"(d[3])
        : "r"(a[0]), "r"(a[1]), "r"(a[2]), "r"(a[3]), "r"(b[0]), "r"(b[1]));
}

__device__ __forceinline__ void ldsm_x4(unsigned* a, const void* p)
{
    unsigned addr = (unsigned)__cvta_generic_to_shared(p);
    asm volatile("ldmatrix.sync.aligned.m8n8.x4.shared.b16 {%0,%1,%2,%3}, [%4];"
                 : "=r"(a[0]), "=r"(a[1]), "=r"(a[2]), "=r"(a[3]) : "r"(addr));
}

__device__ __forceinline__ void cp16(void* dst_smem, const void* src)
{
    unsigned d = (unsigned)__cvta_generic_to_shared(dst_smem);
    asm volatile("cp.async.cg.shared.global [%0], [%1], 16;\n" :: "r"(d), "l"(src));
}
#define CP_COMMIT() asm volatile("cp.async.commit_group;\n")
#define CP_WAIT0()  asm volatile("cp.async.wait_group 0;\n")

__device__ __forceinline__ int kv_src_row(int kc) { return kc + ((kc >> 6) << 6); }

__device__ __forceinline__ float ex2f(float x)
{
    float y;
    asm("ex2.approx.f32 %0, %1;" : "=f"(y) : "f"(x));
    return y;
}

__device__ __forceinline__ void ffma2add(float& a0, float& a1,
                                         float x0, float x1, float y0, float y1)
{
    asm("{\n\t.reg .b64 ra, rx, ry, rt;\n\t"
        "mov.b64 rx, {%2,%3};\n\t"
        "mov.b64 ry, {%4,%5};\n\t"
        "fma.rn.f32x2 rt, ry, %6, rx;\n\t"
        "mov.b64 ra, {%0,%1};\n\t"
        "add.rn.f32x2 ra, ra, rt;\n\t"
        "mov.b64 {%0,%1}, ra;\n\t}"
        : "+f"(a0), "+f"(a1)
        : "f"(x0), "f"(x1), "f"(y0), "f"(y1), "l"(INV2_BITS));
}

__device__ __forceinline__ void fadd2(float& a0, float& a1, float d0, float d1)
{
    asm("{\n\t.reg .b64 ra, rd;\n\t"
        "mov.b64 ra, {%0,%1};\n\t"
        "mov.b64 rd, {%2,%3};\n\t"
        "add.rn.f32x2 ra, ra, rd;\n\t"
        "mov.b64 {%0,%1}, ra;\n\t}"
        : "+f"(a0), "+f"(a1) : "f"(d0), "f"(d1));
}

__device__ __forceinline__ unsigned exp_cvt(unsigned raw, float M2, float iz)
{
    float2 f = __bfloat1622float2(*(__nv_bfloat162*)&raw);
    float p0 = ex2f(__fmaf_rn(f.x, SC2, -M2)) * iz;
    float p1 = ex2f(__fmaf_rn(f.y, SC2, -M2)) * iz;
    __nv_bfloat162 b2 = __floats2bfloat162_rn(p0, p1);
    return *(unsigned*)&b2;
}

// ---------------- merged prep: x split + W splits (paired layout) ----------------
#define NX (SL * DIM)
#define NW ((DIM / 4) * DIM)

__device__ __forceinline__ void do_splitpack_h(const float* src, uint2* p0, uint2* p1, int i)
{
    const int N = DIM;
    int rowblk = i / N, n = i - rowblk * N;
    int c = rowblk >> 3, r8 = rowblk & 7;
    int kk2 = r8 >> 2, tig = r8 & 3;
    int kp0 = c * 16 + kk2 * 8 + tig;
    int kps[2] = {kp0, kp0 + 4};
    unsigned uh[2], ul[2];
#pragma unroll
    for (int j = 0; j < 2; j++) {
        float f0 = src[(size_t)(2 * kps[j]) * N + n];
        float f1 = src[(size_t)(2 * kps[j] + 1) * N + n];
        __half h0 = __float2half_rn(f0), h1 = __float2half_rn(f1);
        __half l0 = __float2half_rn((f0 - __half2float(h0)) * LOSCALE);
        __half l1 = __float2half_rn((f1 - __half2float(h1)) * LOSCALE);
        __half2 ph = __halves2half2(h0, h1);
        __half2 pl = __halves2half2(l0, l1);
        uh[j] = *(unsigned*)&ph;
        ul[j] = *(unsigned*)&pl;
    }
    p0[i] = make_uint2(uh[0], uh[1]);
    p1[i] = make_uint2(ul[0], ul[1]);
}

__device__ __forceinline__ void do_splitpack_b(const float* src, uint2* p0, uint2* p1, int i)
{
    const int N = DIM;
    int rowblk = i / N, n = i - rowblk * N;
    int c = rowblk >> 3, r8 = rowblk & 7;
    int kk2 = r8 >> 2, tig = r8 & 3;
    int kp0 = c * 16 + kk2 * 8 + tig;
    int kps[2] = {kp0, kp0 + 4};
    unsigned uh[2], ul[2];
#pragma unroll
    for (int j = 0; j < 2; j++) {
        float f0 = src[(size_t)(2 * kps[j]) * N + n];
        float f1 = src[(size_t)(2 * kps[j] + 1) * N + n];
        __nv_bfloat16 h0 = __float2bfloat16(f0), h1 = __float2bfloat16(f1);
        __nv_bfloat16 l0 = __float2bfloat16(f0 - __bfloat162float(h0));
        __nv_bfloat16 l1 = __float2bfloat16(f1 - __bfloat162float(h1));
        __nv_bfloat162 ph = __halves2bfloat162(h0, h1);
        __nv_bfloat162 pl = __halves2bfloat162(l0, l1);
        uh[j] = *(unsigned*)&ph;
        ul[j] = *(unsigned*)&pl;
    }
    p0[i] = make_uint2(uh[0], uh[1]);
    p1[i] = make_uint2(ul[0], ul[1]);
}

__global__ void prep_kernel(const float* __restrict__ x,
                            const float* __restrict__ Wq, const float* __restrict__ Wk,
                            const float* __restrict__ Wv, const float* __restrict__ Wo)
{
    int i = blockIdx.x * blockDim.x + threadIdx.x;
    if (i < NX) {
        float f = x[i];
        __half a = __float2half_rn(f);
        float r = f - __half2float(a);
        g_xh[0][i] = a;
        g_xh[1][i] = __float2half_rn(r * LOSCALE);
        return;
    }
    i -= NX;
    if (i < NW) { do_splitpack_h(Wq, g_whp[0], g_whp[1], i); return; }
    i -= NW;
    if (i < NW) { do_splitpack_h(Wk, g_whp[2], g_whp[3], i); return; }
    i -= NW;
    if (i < NW) { do_splitpack_h(Wv, g_whp[4], g_whp[5], i); return; }
    i -= NW;
    if (i < NW) { do_splitpack_b(Wo, g_wop[0], g_wop[1], i); }
}

// ---------------- merged QKV: fp16 3-term split GEMM (one launch, 3 ops) ----------
#define SMF (2*2*128*40*2 + 2*2*8*132*8)   // 74752
__global__ void __launch_bounds__(256) gemm_qkv(
    const float* __restrict__ bq, const float* __restrict__ bk,
    const float* __restrict__ bv)
{
    extern __shared__ char sm[];
    typedef __half ATile[2][128][40];
    typedef uint2 BTile[2][8][132];
    ATile* As = (ATile*)sm;
    BTile* Bs = (BTile*)(sm + 2 * 2 * 128 * 40 * 2);

    const int tid = threadIdx.x;
    const int warp = tid >> 5, lane = tid & 31;
    const int wm = warp >> 1, wn = warp & 1;
    const int group = lane >> 2, tig = lane & 3;

    const int by = blockIdx.y;
    const int op = (by < 50) ? 0 : ((by < 75) ? 1 : 2);
    const int myi = (op == 0) ? by : ((op == 1) ? by - 50 : by - 75);
    const int m0 = myi * 128, n0 = blockIdx.x * 128;

    const uint2* Bp[2];
    const float* bias;
    if (op == 0)      { Bp[0] = g_whp[0]; Bp[1] = g_whp[1]; bias = bq; }
    else if (op == 1) { Bp[0] = g_whp[2]; Bp[1] = g_whp[3]; bias = bk; }
    else              { Bp[0] = g_whp[4]; Bp[1] = g_whp[5]; bias = bv; }

    const int lrow = (lane & 7) + ((lane >> 3) & 1) * 8;
    const int lcol = (lane >> 4) * 8;

    const __half* Ap[2] = {g_xh[0], g_xh[1]};
    const int rA = tid >> 2;
    const int cA = (tid & 3) * 8;
    const int r8B = tid >> 5;
    const int cqB = lane * 2;

    int srcRow[2];
#pragma unroll
    for (int i = 0; i < 2; i++) {
        int o = m0 + rA + i * 64;
        srcRow[i] = (op == 0) ? o : kv_src_row(o);
    }

    auto issue = [&](int k0, int buf) {
        const int c = k0 >> 5;
#pragma unroll
        for (int p = 0; p < 2; p++) {
#pragma unroll
            for (int i = 0; i < 2; i++) {
                int r = rA + i * 64;
                cp16(&As[buf][p][r][cA], &Ap[p][(size_t)srcRow[i] * DIM + k0 + cA]);
            }
#pragma unroll
            for (int i = 0; i < 2; i++) {
                int cq = cqB + i * 64;
                cp16(&Bs[buf][p][r8B][cq],
                     &Bp[p][((size_t)c * 8 + r8B) * DIM + n0 + cq]);
            }
        }
    };

    float acc[2][8][4] = {};

    issue(0, 0);
    CP_COMMIT();
    int buf = 0;

    for (int k0 = 0; k0 < DIM; k0 += 32) {
        CP_WAIT0();
        __syncthreads();
        if (k0 + 32 < DIM) {
            issue(k0 + 32, buf ^ 1);
            CP_COMMIT();
        }

        unsigned a[2][2][2][4];
#pragma unroll
        for (int p = 0; p < 2; p++)
#pragma unroll
            for (int mt = 0; mt < 2; mt++)
#pragma unroll
                for (int kk2 = 0; kk2 < 2; kk2++)
                    ldsm_x4(a[p][mt][kk2],
                            &As[buf][p][wm * 32 + mt * 16 + lrow][kk2 * 16 + lcol]);

#pragma unroll
        for (int nt = 0; nt < 8; nt++) {
            const int n = wn * 64 + nt * 8 + group;
            float d0[2][4] = {};
            float d1[2][4] = {};
#pragma unroll
            for (int kk2 = 0; kk2 < 2; kk2++) {
                uint2 v0 = Bs[buf][0][kk2 * 4 + tig][n];
                uint2 v1 = Bs[buf][1][kk2 * 4 + tig][n];
#pragma unroll
                for (int mt = 0; mt < 2; mt++) {
                    mma_f16(d0[mt], a[0][mt][kk2], &v0.x);
                    mma_f16(d1[mt], a[0][mt][kk2], &v1.x);
                    mma_f16(d1[mt], a[1][mt][kk2], &v0.x);
                }
            }
#pragma unroll
            for (int mt = 0; mt < 2; mt++) {
                ffma2add(acc[mt][nt][0], acc[mt][nt][1],
                         d0[mt][0], d0[mt][1], d1[mt][0], d1[mt][1]);
                ffma2add(acc[mt][nt][2], acc[mt][nt][3],
                         d0[mt][2], d0[mt][3], d1[mt][2], d1[mt][3]);
            }
        }
        buf ^= 1;
    }

    float* C = (op == 0) ? g_qraw : g_kraw;
#pragma unroll
    for (int mt = 0; mt < 2; mt++) {
        const int row = m0 + wm * 32 + mt * 16 + group;
#pragma unroll
        for (int nt = 0; nt < 8; nt++) {
            const int col = n0 + wn * 64 + nt * 8 + tig * 2;
            float b0 = bias[col], b1 = bias[col + 1];
            if (op == 2) {
                *(__nv_bfloat162*)&g_vb[(size_t)row * DIM + col] =
                    __floats2bfloat162_rn(acc[mt][nt][0] + b0, acc[mt][nt][1] + b1);
                *(__nv_bfloat162*)&g_vb[(size_t)(row + 8) * DIM + col] =
                    __floats2bfloat162_rn(acc[mt][nt][2] + b0, acc[mt][nt][3] + b1);
            } else {
                C[(size_t)row * DIM + col]           = acc[mt][nt][0] + b0;
                C[(size_t)row * DIM + col + 1]       = acc[mt][nt][1] + b1;
                C[(size_t)(row + 8) * DIM + col]     = acc[mt][nt][2] + b0;
                C[(size_t)(row + 8) * DIM + col + 1] = acc[mt][nt][3] + b1;
            }
        }
    }
}

// ---------------- bf16 2-term GEMM for Wo ----------------
#define SMW (2*128*40*2 + 2*2*8*132*8)     // 54272
__global__ void __launch_bounds__(256) gemm_wo(
    const float* __restrict__ bias, float* __restrict__ C)
{
    extern __shared__ char sm[];
    typedef __nv_bfloat16 ATile[128][40];
    typedef uint2 BTile[2][8][132];
    ATile* As = (ATile*)sm;
    BTile* Bs = (BTile*)(sm + 2 * 128 * 40 * 2);

    const int tid = threadIdx.x;
    const int warp = tid >> 5, lane = tid & 31;
    const int wm = warp >> 1, wn = warp & 1;
    const int group = lane >> 2, tig = lane & 3;
    const int m0 = blockIdx.y * 128, n0 = blockIdx.x * 128;

    const int lrow = (lane & 7) + ((lane >> 3) & 1) * 8;
    const int lcol = (lane >> 4) * 8;

    const uint2* Bp[2] = {g_wop[0], g_wop[1]};
    const int rA = tid >> 2;
    const int cA = (tid & 3) * 8;
    const int r8B = tid >> 5;
    const int cqB = lane * 2;

    auto issue = [&](int k0, int buf) {
        const int c = k0 >> 5;
#pragma unroll
        for (int i = 0; i < 2; i++) {
            int r = rA + i * 64;
            cp16(&As[buf][r][cA], &g_aob[(size_t)(m0 + r) * DIM + k0 + cA]);
        }
#pragma unroll
        for (int p = 0; p < 2; p++)
#pragma unroll
            for (int i = 0; i < 2; i++) {
                int cq = cqB + i * 64;
                cp16(&Bs[buf][p][r8B][cq],
                     &Bp[p][((size_t)c * 8 + r8B) * DIM + n0 + cq]);
            }
    };

    float acc[2][8][4] = {};
    issue(0, 0);
    CP_COMMIT();
    int buf = 0;

    for (int k0 = 0; k0 < DIM; k0 += 32) {
        CP_WAIT0();
        __syncthreads();
        if (k0 + 32 < DIM) {
            issue(k0 + 32, buf ^ 1);
            CP_COMMIT();
        }

        unsigned a[2][2][4];
#pragma unroll
        for (int mt = 0; mt < 2; mt++)
#pragma unroll
            for (int kk2 = 0; kk2 < 2; kk2++)
                ldsm_x4(a[mt][kk2], &As[buf][wm * 32 + mt * 16 + lrow][kk2 * 16 + lcol]);

#pragma unroll
        for (int nt = 0; nt < 8; nt++) {
            const int n = wn * 64 + nt * 8 + group;
            float d[2][4] = {};
#pragma unroll
            for (int kk2 = 0; kk2 < 2; kk2++) {
                uint2 v0 = Bs[buf][0][kk2 * 4 + tig][n];
                uint2 v1 = Bs[buf][1][kk2 * 4 + tig][n];
#pragma unroll
                for (int mt = 0; mt < 2; mt++) {
                    mma_bf16(d[mt], a[mt][kk2], &v0.x);
                    mma_bf16(d[mt], a[mt][kk2], &v1.x);
                }
            }
#pragma unroll
            for (int mt = 0; mt < 2; mt++) {
                fadd2(acc[mt][nt][0], acc[mt][nt][1], d[mt][0], d[mt][1]);
                fadd2(acc[mt][nt][2], acc[mt][nt][3], d[mt][2], d[mt][3]);
            }
        }
        buf ^= 1;
    }

#pragma unroll
    for (int mt = 0; mt < 2; mt++) {
        const int row = m0 + wm * 32 + mt * 16 + group;
#pragma unroll
        for (int nt = 0; nt < 8; nt++) {
            const int col = n0 + wn * 64 + nt * 8 + tig * 2;
            float b0 = bias[col], b1 = bias[col + 1];
            C[(size_t)row * DIM + col]           = acc[mt][nt][0] + b0;
            C[(size_t)row * DIM + col + 1]       = acc[mt][nt][1] + b1;
            C[(size_t)(row + 8) * DIM + col]     = acc[mt][nt][2] + b0;
            C[(size_t)(row + 8) * DIM + col + 1] = acc[mt][nt][3] + b1;
        }
    }
}

// ---------------- merged RMSNorm/RoPE + V pack ----------------
__global__ void rmsvp_kernel(const float* __restrict__ gq, const float* __restrict__ gk,
                             const float* __restrict__ freqs)
{
    const int bx = blockIdx.x;
    const int tid = threadIdx.x;

    if (bx >= SL) {
        int i = (bx - SL) * TPB + tid;
        if (i < (LK / 4) * DIM) {
            int rowblk = i / DIM, n = i - rowblk * DIM;
            int c64 = rowblk >> 4, r = rowblk & 15;
            int g = r >> 2, tig = r & 3;
            int kp0 = c64 * 32 + g * 8 + tig;
            int kp1 = kp0 + 4;
            __nv_bfloat162 a2 = __halves2bfloat162(g_vb[(size_t)(2 * kp0) * DIM + n],
                                                   g_vb[(size_t)(2 * kp0 + 1) * DIM + n]);
            __nv_bfloat162 b2 = __halves2bfloat162(g_vb[(size_t)(2 * kp1) * DIM + n],
                                                   g_vb[(size_t)(2 * kp1 + 1) * DIM + n]);
            g_vpk[i] = make_uint2(*(unsigned*)&a2, *(unsigned*)&b2);
        }
        return;
    }

    const int l = bx;
    const int fi = l >> 6;
    const int rem = l & 63;
    const bool keep = (fi & 1) == 0;
    const int kc = (fi >> 1) * 64 + rem;

    const float* qr = g_qraw + (size_t)l * DIM;
    const float* kr = g_kraw + (size_t)kc * DIM;

    float sq = 0.f, sk = 0.f;
    for (int i = tid; i < DIM; i += TPB) {
        float a = qr[i]; sq += a * a;
        if (keep) { float b = kr[i]; sk += b * b; }
    }
    __shared__ float rq[8], rk[8];
#pragma unroll
    for (int off = 16; off; off >>= 1) {
        sq += __shfl_xor_sync(0xffffffffu, sq, off);
        sk += __shfl_xor_sync(0xffffffffu, sk, off);
    }
    if ((tid & 31) == 0) { rq[tid >> 5] = sq; rk[tid >> 5] = sk; }
    __syncthreads();
    if (tid == 0) {
        float tq = 0.f, tk = 0.f;
        for (int i = 0; i < 8; i++) { tq += rq[i]; tk += rk[i]; }
        rq[0] = rsqrtf(tq / DIM + 1e-6f);
        rk[0] = rsqrtf(tk / DIM + 1e-6f);
    }
    __syncthreads();
    const float invq = rq[0], invk = rk[0];

    const int hi = rem >> 3, wi = rem & 7;

    for (int e = tid; e < NHD * 64; e += TPB) {
        const int n = e >> 6;
        const int p = e & 63;
        float ang;
        if (p < 22)      ang = freqs[fi * 64 + p];
        else if (p < 43) ang = freqs[hi * 64 + p];
        else             ang = freqs[wi * 64 + p];
        float s, c;
        sincosf(ang, &s, &c);
        const int j0 = n * HD + 2 * p;

        float q0 = qr[j0] * invq * gq[j0];
        float q1 = qr[j0 + 1] * invq * gq[j0 + 1];
        g_qb[(size_t)l * DIM + j0]     = __float2bfloat16(q0 * c - q1 * s);
        g_qb[(size_t)l * DIM + j0 + 1] = __float2bfloat16(q0 * s + q1 * c);

        if (keep) {
            float k0v = kr[j0] * invk * gk[j0];
            float k1v = kr[j0 + 1] * invk * gk[j0 + 1];
            g_kb[(size_t)kc * DIM + j0]     = __float2bfloat16(k0v * c - k1v * s);
            g_kb[(size_t)kc * DIM + j0 + 1] = __float2bfloat16(k0v * s + k1v * c);
        }
    }
}

// ---------------- scores via HMMA, 64-k chunked smem (high occupancy) ----------
// 2 chunks of 64 k; tiles 128x72 each (36,864 B dynamic -> ~5-6 CTAs/SM).
// Accumulation order over kk identical to full-K version (bit-identical).
#define SMS (2 * 128 * 72 * 2)   // 36864
__global__ void __launch_bounds__(256) score_gemm_mma(void)
{
    extern __shared__ char sm[];
    typedef __nv_bfloat16 Row72[72];
    Row72* Qs = (Row72*)sm;
    Row72* Ks = (Row72*)(sm + 128 * 72 * 2);
    __shared__ float sm_m[128][2], sm_s[128][2];

    const int h = blockIdx.z;
    const int mb0 = blockIdx.y * 128, n0 = blockIdx.x * 128;
    const int tid = threadIdx.x;
    const int warp = tid >> 5, lane = tid & 31;
    const int wm = warp >> 1, wn = warp & 1;
    const int group = lane >> 2, tig = lane & 3;

    const int lrow = (lane & 7) + ((lane >> 3) & 1) * 8;
    const int lcol = (lane >> 4) * 8;
    const int brow = ((lane >> 4) << 3) + (lane & 7);
    const int bcol = ((lane >> 3) & 1) * 8;

    const __nv_bfloat16* Q  = g_qb + h * HD;
    const __nv_bfloat16* Kb = g_kb + h * HD;

    // per-thread copy coords: 2 threads per row, each covers 32 cols = 4 x 16B
    const int rL = tid >> 1;            // 0..127
    const int cL = (tid & 1) * 32;      // 0 or 32

    float acc[2][8][4] = {};

    for (int k0 = 0; k0 < HD; k0 += 64) {
#pragma unroll
        for (int i = 0; i < 4; i++) {
            int c = cL + i * 8;
            cp16(&Qs[rL][c], &Q [(size_t)(mb0 + rL) * DIM + k0 + c]);
            cp16(&Ks[rL][c], &Kb[(size_t)(n0 + rL) * DIM + k0 + c]);
        }
        CP_COMMIT();
        CP_WAIT0();
        __syncthreads();

#pragma unroll
        for (int kk = 0; kk < 64; kk += 16) {
            unsigned a[2][4], b[8][2];
#pragma unroll
            for (int mt = 0; mt < 2; mt++)
                ldsm_x4(a[mt], &Qs[wm * 32 + mt * 16 + lrow][kk + lcol]);
#pragma unroll
            for (int ntp = 0; ntp < 4; ntp++) {
                unsigned r4[4];
                ldsm_x4(r4, &Ks[wn * 64 + ntp * 16 + brow][kk + bcol]);
                b[2 * ntp][0] = r4[0]; b[2 * ntp][1] = r4[1];
                b[2 * ntp + 1][0] = r4[2]; b[2 * ntp + 1][1] = r4[3];
            }
#pragma unroll
            for (int mt = 0; mt < 2; mt++)
#pragma unroll
                for (int nt = 0; nt < 8; nt++)
                    mma_bf16(acc[mt][nt], a[mt], b[nt]);
        }
        __syncthreads();
    }

    __nv_bfloat16* S = g_sc + (size_t)h * SL * LK;
#pragma unroll
    for (int mt = 0; mt < 2; mt++) {
#pragma unroll
        for (int hh = 0; hh < 2; hh++) {
            const int rr = wm * 32 + mt * 16 + group + hh * 8;
            const int row = mb0 + rr;
            float xv[16];
            float mx = -1e30f;
#pragma unroll
            for (int nt = 0; nt < 8; nt++) {
                const int col = n0 + wn * 64 + nt * 8 + tig * 2;
                __nv_bfloat162 b2 = __floats2bfloat162_rn(acc[mt][nt][hh * 2],
                                                          acc[mt][nt][hh * 2 + 1]);
                *(__nv_bfloat162*)&S[(size_t)row * LK + col] = b2;
                float2 f = __bfloat1622float2(b2);
                xv[2 * nt]     = f.x * SM_SCALE;
                xv[2 * nt + 1] = f.y * SM_SCALE;
                mx = fmaxf(mx, fmaxf(xv[2 * nt], xv[2 * nt + 1]));
            }
            mx = fmaxf(mx, __shfl_xor_sync(0xffffffffu, mx, 1));
            mx = fmaxf(mx, __shfl_xor_sync(0xffffffffu, mx, 2));
            const float mxl = mx * LOG2E;
            float sum = 0.f;
#pragma unroll
            for (int c = 0; c < 16; c++)
                sum += ex2f(__fmaf_rn(xv[c], LOG2E, -mxl));
            sum += __shfl_xor_sync(0xffffffffu, sum, 1);
            sum += __shfl_xor_sync(0xffffffffu, sum, 2);
            if (tig == 0) { sm_m[rr][wn] = mx; sm_s[rr][wn] = sum; }
        }
    }
    __syncthreads();
    if (tid < 128) {
        float m0v = sm_m[tid][0], m1v = sm_m[tid][1];
        float M = fmaxf(m0v, m1v);
        float Sv = sm_s[tid][0] * ex2f((m0v - M) * LOG2E)
                 + sm_s[tid][1] * ex2f((m1v - M) * LOG2E);
        size_t base = ((size_t)h * SL + mb0 + tid) * NKB + blockIdx.x;
        g_pm[base] = M;
        g_ps[base] = Sv;
    }
}

// ---------------- combine partial stats -> per-row M*log2e, 1/Z ----------------
__global__ void combine_kernel(void)
{
    int idx = blockIdx.x * blockDim.x + threadIdx.x;
    if (idx >= NHD * SL) return;
    const float* pm = g_pm + (size_t)idx * NKB;
    const float* ps = g_ps + (size_t)idx * NKB;
    float M = -1e30f;
#pragma unroll
    for (int b = 0; b < NKB; b++) M = fmaxf(M, pm[b]);
    float Z = 0.f;
#pragma unroll
    for (int b = 0; b < NKB; b++) Z += ps[b] * ex2f((pm[b] - M) * LOG2E);
    g_M2[idx] = M * LOG2E;
    g_iz[idx] = 1.f / Z;
}

// ---------------- PV via HMMA; paired-V; ex2 probs; double-buffered ----------------
#define SMPV (2*128*72*2 + 2*16*132*8)   // 70656
__global__ void __launch_bounds__(256) pv_gemm_mma(void)
{
    extern __shared__ char sm[];
    typedef __nv_bfloat16 PRow[72];
    typedef uint2 VRow[132];
    PRow* Praw = (PRow*)sm;
    VRow* Vps  = (VRow*)(sm + 2 * 128 * 72 * 2);
    __shared__ float sMr[128], sZr[128];

    const int h = blockIdx.z;
    const int m0 = blockIdx.y * 128;
    const int tid = threadIdx.x;
    const int warp = tid >> 5, lane = tid & 31;
    const int group = lane >> 2, tig = lane & 3;

    const __nv_bfloat16* P = g_sc + (size_t)h * SL * LK;
    const uint2* Vg = g_vpk + h * HD;

    if (tid < 128) {
        int row = h * SL + m0 + tid;
        sMr[tid] = g_M2[row];
        sZr[tid] = g_iz[row];
    }

    auto issue = [&](int k0, int buf) {
        const int c64 = k0 >> 6;
#pragma unroll
        for (int i = 0; i < 4; i++) {
            int idx = tid + i * 256;
            int r = idx >> 3, c = (idx & 7) * 8;
            cp16(&Praw[buf * 128 + r][c], &P[(size_t)(m0 + r) * LK + k0 + c]);
        }
#pragma unroll
        for (int i = 0; i < 4; i++) {
            int idx = tid + i * 256;
            int rb = idx >> 6, cq = (idx & 63) * 2;
            cp16(&Vps[buf * 16 + rb][cq], &Vg[((size_t)c64 * 16 + rb) * DIM + cq]);
        }
    };

    issue(0, 0);
    CP_COMMIT();
    int buf = 0;

    __syncthreads();
    const int rloc = warp * 16 + group;
    const float M0 = sMr[rloc], iz0 = sZr[rloc];
    const float M1 = sMr[rloc + 8], iz1 = sZr[rloc + 8];

    float acc[16][4] = {};

    for (int k0 = 0; k0 < LK; k0 += 64) {
        CP_WAIT0();
        __syncthreads();
        if (k0 + 64 < LK) {
            issue(k0 + 64, buf ^ 1);
            CP_COMMIT();
        }

#pragma unroll
        for (int kk = 0; kk < 64; kk += 16) {
            const int g = kk >> 4;
            unsigned a[4];
            a[0] = exp_cvt(*(const unsigned*)&Praw[buf * 128 + rloc][kk + tig * 2], M0, iz0);
            a[1] = exp_cvt(*(const unsigned*)&Praw[buf * 128 + rloc + 8][kk + tig * 2], M1, iz1);
            a[2] = exp_cvt(*(const unsigned*)&Praw[buf * 128 + rloc][kk + 8 + tig * 2], M0, iz0);
            a[3] = exp_cvt(*(const unsigned*)&Praw[buf * 128 + rloc + 8][kk + 8 + tig * 2], M1, iz1);
#pragma unroll
            for (int nt = 0; nt < 16; nt++) {
                uint2 v = Vps[buf * 16 + g * 4 + tig][nt * 8 + group];
                mma_bf16(acc[nt], a, &v.x);
            }
        }
        buf ^= 1;
    }

    const int row = m0 + rloc;
#pragma unroll
    for (int nt = 0; nt < 16; nt++) {
        const int col = h * HD + nt * 8 + tig * 2;
        *(__nv_bfloat162*)&g_aob[(size_t)row * DIM + col] =
            __floats2bfloat162_rn(acc[nt][0], acc[nt][1]);
        *(__nv_bfloat162*)&g_aob[(size_t)(row + 8) * DIM + col] =
            __floats2bfloat162_rn(acc[nt][2], acc[nt][3]);
    }
}

// ---------------- launch ----------------
extern "C" void kernel_launch(void* const* d_in, const int* in_sizes, int n_in,
                              void* d_out, int out_size)
{
    const float* x     = (const float*)d_in[0];
    const float* freqs = (const float*)d_in[1];
    const float* Wq    = (const float*)d_in[2];
    const float* bq    = (const float*)d_in[3];
    const float* Wk    = (const float*)d_in[4];
    const float* bk    = (const float*)d_in[5];
    const float* Wv    = (const float*)d_in[6];
    const float* bv    = (const float*)d_in[7];
    const float* Wo    = (const float*)d_in[8];
    const float* bo    = (const float*)d_in[9];
    const float* gq    = (const float*)d_in[10];
    const float* gk    = (const float*)d_in[11];
    float* out = (float*)d_out;

    cudaFuncSetAttribute(gemm_qkv, cudaFuncAttributeMaxDynamicSharedMemorySize, SMF);
    cudaFuncSetAttribute(gemm_wo, cudaFuncAttributeMaxDynamicSharedMemorySize, SMW);
    cudaFuncSetAttribute(score_gemm_mma, cudaFuncAttributeMaxDynamicSharedMemorySize, SMS);
    cudaFuncSetAttribute(pv_gemm_mma, cudaFuncAttributeMaxDynamicSharedMemorySize, SMPV);

    dim3 blk(TPB);

    const int prep_total = NX + 4 * NW;
    prep_kernel<<<(prep_total + TPB - 1) / TPB, blk>>>(x, Wq, Wk, Wv, Wo);

    dim3 gQKV(DIM / 128, 100);
    gemm_qkv<<<gQKV, blk, SMF>>>(bq, bk, bv);

    const int vpk_blocks = ((LK / 4) * DIM + TPB - 1) / TPB;
    rmsvp_kernel<<<SL + vpk_blocks, blk>>>(gq, gk, freqs);

    dim3 gScore(LK / 128, SL / 128, NHD);     // (25, 50, 12)
    score_gemm_mma<<<gScore, blk, SMS>>>();

    combine_kernel<<<(NHD * SL + TPB - 1) / TPB, blk>>>();

    dim3 gPV(1, SL / 128, NHD);
    pv_gemm_mma<<<gPV, blk, SMPV>>>();

    dim3 gWo(DIM / 128, SL / 128);
    gemm_wo<<<gWo, blk, SMW>>>(bo, out);
}